// round 9
// baseline (speedup 1.0000x reference)
#include <cuda_runtime.h>
#include <cstddef>

#define TLEN 512
#define NV 21
#define NC 32
#define TC 16
#define NTHR 512

#define HT_S 436      // Ht row stride (109 quads, odd)
#define SC_S 388      // sc row stride (97 quads, odd)
#define FCS_S 196     // fcs row stride (49 quads, odd)

// smem float offsets (per-CTA 113,728 B -> 2 CTAs/SM)
#define OFF_R1 0          // Ht[32][436]=13952 ; later fcs[64][196]=12544
#define OFF_R2 13952      // bufAx[20][48]=960 ; later sc[32][388]=12416
#define OFF_XD 26368      // bufXd[20][48]=960 ; later red[1024] (spills into AS)
#define OFF_AS 27328      // A (464)
#define OFF_PP 27792      // pp (640)
#define SMEM_FLOATS 28432
#define SMEM_BYTES (SMEM_FLOATS*4)

#define PP_TW0 0
#define PP_BK0 192
#define PP_BK1 288
#define PP_TB0 384
#define PP_TB1 416
#define PP_RW 448
#define PP_RB 512
#define PP_FCB 544
#define PP_TOT 608

typedef unsigned long long u64;
__device__ __forceinline__ u64 fma2(u64 a,u64 b,u64 c){u64 d;asm("fma.rn.f32x2 %0,%1,%2,%3;":"=l"(d):"l"(a),"l"(b),"l"(c));return d;}
__device__ __forceinline__ u64 dup2(float v){u64 r;asm("mov.b64 %0,{%1,%1};":"=l"(r):"f"(v));return r;}
__device__ __forceinline__ float2 un2(u64 p){float2 f;asm("mov.b64 {%0,%1},%2;":"=f"(f.x),"=f"(f.y):"l"(p));return f;}

__device__ float g_A[464];
__device__ float g_tw1f[NC*3*NC];
__device__ float g_fcw2[64*768];
__device__ float g_pp[PP_TOT];

__global__ void prep_kernel(
    const float* __restrict__ gcn_w0,const float* __restrict__ gcn_b0,
    const float* __restrict__ tcn_w0,const float* __restrict__ tcn_b0,
    const float* __restrict__ bn_g0,const float* __restrict__ bn_b0,
    const float* __restrict__ bn_m0,const float* __restrict__ bn_v0,
    const float* __restrict__ res_w,const float* __restrict__ res_b,
    const float* __restrict__ res_bn_g,const float* __restrict__ res_bn_b,
    const float* __restrict__ res_bn_m,const float* __restrict__ res_bn_v,
    const float* __restrict__ gcn_w1,const float* __restrict__ gcn_b1,
    const float* __restrict__ tcn_w1,const float* __restrict__ tcn_b1,
    const float* __restrict__ bn_g1,const float* __restrict__ bn_b1,
    const float* __restrict__ bn_m1,const float* __restrict__ bn_v1,
    const float* __restrict__ fc_w,const float* __restrict__ fc_b)
{
    int gtid=blockIdx.x*blockDim.x+threadIdx.x, nthr=gridDim.x*blockDim.x;
    for(int idx=gtid;idx<64*768;idx+=nthr){
        int j=idx/768,kp=idx-j*768,c=kp/24,v=kp-c*24;
        g_fcw2[idx]=(v<NV)?fc_w[j*(NC*NV)+c*NV+v]:0.f;
    }
    for(int idx=gtid;idx<NC*3*NC;idx+=nthr){
        int o=idx&31,ik=idx>>5,i=ik/3,k=ik-i*3;
        float s1=bn_g1[o]*rsqrtf(bn_v1[o]+1e-5f),s=0.f;
        for(int j=0;j<NC;j++) s+=tcn_w1[(o*NC+j)*3+k]*gcn_w1[j*NC+i];
        g_tw1f[(i*3+k)*NC+o]=s*s1;
    }
    if(gtid==0){
        float Ad[NV][NV];
        for(int i=0;i<NV;i++)for(int j=0;j<NV;j++)Ad[i][j]=(i==j)?1.f:0.f;
        const int conn[20][2]={{0,1},{1,2},{2,3},{3,4},{0,5},{5,6},{6,7},{7,8},
            {0,9},{9,10},{10,11},{11,12},{0,13},{13,14},{14,15},{15,16},
            {0,17},{17,18},{18,19},{19,20}};
        for(int e=0;e<20;e++){Ad[conn[e][0]][conn[e][1]]=1.f;Ad[conn[e][1]][conn[e][0]]=1.f;}
        float d[NV];
        for(int i=0;i<NV;i++){float s=0.f;for(int j=0;j<NV;j++)s+=Ad[i][j];d[i]=rsqrtf(s);}
        for(int i=0;i<464;i++)g_A[i]=0.f;
        for(int i=0;i<NV;i++)for(int j=0;j<NV;j++)g_A[i*22+j]=d[i]*Ad[i][j]*d[j];
    }
    if(gtid<NC){
        int o=gtid;
        float s0=bn_g0[o]*rsqrtf(bn_v0[o]+1e-5f);
        float s1=bn_g1[o]*rsqrtf(bn_v1[o]+1e-5f);
        for(int k=0;k<3;k++){
            for(int ci=0;ci<2;ci++){
                float s=0.f;
                for(int i=0;i<NC;i++)s+=tcn_w0[(o*NC+i)*3+k]*gcn_w0[i*2+ci];
                g_pp[PP_TW0+(k*2+ci)*NC+o]=s*s0;
            }
            float sb=0.f;
            for(int i=0;i<NC;i++)sb+=tcn_w0[(o*NC+i)*3+k]*gcn_b0[i];
            g_pp[PP_BK0+k*NC+o]=sb*s0;
            float sb1=0.f;
            for(int j=0;j<NC;j++)sb1+=tcn_w1[(o*NC+j)*3+k]*gcn_b1[j];
            g_pp[PP_BK1+k*NC+o]=sb1*s1;
        }
        g_pp[PP_TB0+o]=(tcn_b0[o]-bn_m0[o])*s0+bn_b0[o];
        g_pp[PP_TB1+o]=(tcn_b1[o]-bn_m1[o])*s1+bn_b1[o];
        float sr=res_bn_g[o]*rsqrtf(res_bn_v[o]+1e-5f);
        g_pp[PP_RW+o]=res_w[o*2+0]*sr;
        g_pp[PP_RW+NC+o]=res_w[o*2+1]*sr;
        g_pp[PP_RB+o]=(res_b[o]-res_bn_m[o])*sr+res_bn_b[o];
    }
    if(gtid>=64&&gtid<128)g_pp[PP_FCB+gtid-64]=fc_b[gtid-64];
}

__global__ __launch_bounds__(NTHR,2)
void stgcn_kernel(const float* __restrict__ x,float* __restrict__ outp)
{
    extern __shared__ float smem[];
    float* R1=smem+OFF_R1;          // Ht / fcs
    float* R2=smem+OFF_R2;          // bufAx / sc
    float* bufXd=smem+OFF_XD;       // later red
    float* As=smem+OFF_AS;
    float* pp=smem+OFF_PP;

    const int tid=threadIdx.x, lane=tid&31, wid=tid>>5;
    const int t0=blockIdx.x*TC, hand=blockIdx.y, b=blockIdx.z;

    constexpr int DEG[NV]={6,3,3,3,2,3,3,3,2,3,3,3,2,3,3,3,2,3,3,3,2};
    constexpr int NBR[NV][6]={
        {0,1,5,9,13,17},{0,1,2,0,0,0},{1,2,3,0,0,0},{2,3,4,0,0,0},{3,4,0,0,0,0},
        {0,5,6,0,0,0},{5,6,7,0,0,0},{6,7,8,0,0,0},{7,8,0,0,0,0},
        {0,9,10,0,0,0},{9,10,11,0,0,0},{10,11,12,0,0,0},{11,12,0,0,0,0},
        {0,13,14,0,0,0},{13,14,15,0,0,0},{14,15,16,0,0,0},{15,16,0,0,0,0},
        {0,17,18,0,0,0},{17,18,19,0,0,0},{18,19,20,0,0,0},{19,20,0,0,0,0}};

    // prolog
    for(int i=tid;i<464;i+=NTHR)As[i]=g_A[i];
    for(int i=tid;i<PP_TOT;i+=NTHR)pp[i]=g_pp[i];

    // x fill: bufXd[s][ci*24+v], s=0..19, t=t0+s-2
    for(int idx=tid;idx<20*NV;idx+=NTHR){
        int s=idx/NV,v=idx-s*NV,t=t0+s-2;
        float2 xv=make_float2(0.f,0.f);
        if(t>=0&&t<TLEN)xv=*(const float2*)(x+(((size_t)(b*TLEN+t)*2+hand)*NV+v)*2);
        bufXd[s*48+v]=xv.x; bufXd[s*48+24+v]=xv.y;
    }
    __syncthreads();

    // stage A: A-mix -> bufAx (in R2)
    float* bufAx=R2;
    for(int sA=wid;sA<20;sA+=16){
        if(lane<24){
            float s0=0.f,s1=0.f;
            if(lane<NV){
                const float* Ar=As+lane*22; const float* xr=bufXd+sA*48;
                #pragma unroll
                for(int u=0;u<NV;u++){float a=Ar[u];s0+=a*xr[u];s1+=a*xr[24+u];}
            }
            bufAx[sA*48+lane]=s0; bufAx[sA*48+24+lane]=s1;
        }
    }
    __syncthreads();

    // stage B: folded tcn0+res+relu -> Ht[o][sB*24+..], sB 0..17
    {
        const int o=lane;
        const float bk00=pp[PP_BK0+o],bk02=pp[PP_BK0+64+o];
        const float biasAll=pp[PP_TB0+o]+bk00+pp[PP_BK0+32+o]+bk02+pp[PP_RB+o];
        const u64 rw0d=dup2(pp[PP_RW+o]),rw1d=dup2(pp[PP_RW+32+o]);
        for(int sB=wid;sB<18;sB+=16){
            int t=t0+sB-1;
            float* dst=R1+o*HT_S+sB*24;
            if(t<0||t>=TLEN){
                float4 z=make_float4(0.f,0.f,0.f,0.f);
                #pragma unroll
                for(int m=0;m<6;m++)((float4*)dst)[m]=z;
            }else{
                float bias=biasAll;
                if(t==0)bias-=bk00;
                if(t==TLEN-1)bias-=bk02;
                u64 acc[12],bd=dup2(bias);
                #pragma unroll
                for(int q=0;q<12;q++)acc[q]=bd;
                #pragma unroll
                for(int k=0;k<3;k++)
                    #pragma unroll
                    for(int ci=0;ci<2;ci++){
                        u64 w=dup2(pp[PP_TW0+(k*2+ci)*NC+o]);
                        const ulonglong2* rp=(const ulonglong2*)(bufAx+(sB+k)*48+ci*24);
                        #pragma unroll
                        for(int m=0;m<6;m++){
                            ulonglong2 r2=rp[m];
                            acc[2*m]=fma2(w,r2.x,acc[2*m]);
                            acc[2*m+1]=fma2(w,r2.y,acc[2*m+1]);
                        }
                    }
                const ulonglong2* x0p=(const ulonglong2*)(bufXd+(sB+1)*48);
                const ulonglong2* x1p=(const ulonglong2*)(bufXd+(sB+1)*48+24);
                #pragma unroll
                for(int m=0;m<6;m++){
                    ulonglong2 xa=x0p[m],xb=x1p[m];
                    acc[2*m]=fma2(rw0d,xa.x,acc[2*m]);
                    acc[2*m]=fma2(rw1d,xb.x,acc[2*m]);
                    acc[2*m+1]=fma2(rw0d,xa.y,acc[2*m+1]);
                    acc[2*m+1]=fma2(rw1d,xb.y,acc[2*m+1]);
                }
                #pragma unroll
                for(int m=0;m<6;m++){
                    float2 f0=un2(acc[2*m]),f1=un2(acc[2*m+1]);
                    float v0=fmaxf(f0.x,0.f),v1=fmaxf(f0.y,0.f);
                    float v2=fmaxf(f1.x,0.f),v3=fmaxf(f1.y,0.f);
                    if(m==5){v1=0.f;v2=0.f;v3=0.f;}
                    ((float4*)dst)[m]=make_float4(v0,v1,v2,v3);
                }
            }
        }
    }
    __syncthreads();   // bufAx dead; sc may be written

    // stage D (GEMM): sc[o][2n] = sum_i,kt W[i,kt,o]*Ht[i][2n+24kt], n 0..191
    // thread: og=tid>>6 (4 o each), m=tid&63, n=m+64j (j 0..2)
    {
        const int og=tid>>6, m=tid&63;
        u64 acc[4][3];
        #pragma unroll
        for(int oi=0;oi<4;oi++)
            #pragma unroll
            for(int j=0;j<3;j++)acc[oi][j]=0ull;
        #pragma unroll 1
        for(int i=0;i<NC;i++){
            const float* hrow=R1+i*HT_S+2*m;
            const float4* wp=(const float4*)(g_tw1f+i*96+4*og);
            #pragma unroll
            for(int kt=0;kt<3;kt++){
                float4 wv=__ldg(wp+kt*8);     // +kt*32 floats
                u64 w0=dup2(wv.x),w1=dup2(wv.y),w2=dup2(wv.z),w3=dup2(wv.w);
                #pragma unroll
                for(int j=0;j<3;j++){
                    u64 h=*(const u64*)(hrow+128*j+24*kt);
                    acc[0][j]=fma2(w0,h,acc[0][j]);
                    acc[1][j]=fma2(w1,h,acc[1][j]);
                    acc[2][j]=fma2(w2,h,acc[2][j]);
                    acc[3][j]=fma2(w3,h,acc[3][j]);
                }
            }
        }
        float* sc=R2;
        #pragma unroll
        for(int j=0;j<3;j++){
            int n=m+64*j;
            #pragma unroll
            for(int oi=0;oi<4;oi++)
                *(u64*)(sc+(4*og+oi)*SC_S+2*n)=acc[oi][j];
        }
    }
    __syncthreads();

    // stage D2: A-mix + bias + res + relu, in place on sc rows; s=wid (16 warps)
    {
        float* sc=R2;
        const int o=lane, s=wid, t=t0+s;
        float* row=sc+o*SC_S+s*24;
        float qv[24];
        #pragma unroll
        for(int m=0;m<6;m++){
            float4 f=((const float4*)row)[m];
            qv[4*m]=f.x;qv[4*m+1]=f.y;qv[4*m+2]=f.z;qv[4*m+3]=f.w;
        }
        float bias=pp[PP_TB1+o]+pp[PP_BK1+o]+pp[PP_BK1+32+o]+pp[PP_BK1+64+o];
        if(t==0)bias-=pp[PP_BK1+o];
        if(t==TLEN-1)bias-=pp[PP_BK1+64+o];
        const float4* rp=(const float4*)(R1+o*HT_S+(s+1)*24);
        #pragma unroll
        for(int m=0;m<6;m++){
            float4 rr=rp[m];
            float ov[4];
            #pragma unroll
            for(int k4=0;k4<4;k4++){
                int v=4*m+k4;
                float p=bias+((k4==0)?rr.x:(k4==1)?rr.y:(k4==2)?rr.z:rr.w);
                if(v<NV){
                    #pragma unroll
                    for(int j=0;j<6;j++)
                        if(j<DEG[v])p+=As[v*22+NBR[v][j]]*qv[NBR[v][j]];
                    ov[k4]=fmaxf(p,0.f);
                }else ov[k4]=0.f;
            }
            ((float4*)row)[m]=make_float4(ov[0],ov[1],ov[2],ov[3]);
        }
    }
    __syncthreads();   // Ht dead -> fcs in R1; bufXd/As dead -> red

    // stage E: FC 768->64, 4 chunks of 8 o.
    // warp = (sg=wid>>2: 4 slots, jh=(wid>>1)&1: 32 j, kh=wid&1: k-half)
    // lane = (kq=lane>>3, jg=lane&7); per chunk: olocal = 4kh+kq (1 o).
    {
        float* sc=R2;
        float* fcs=R1;
        float* red=smem+OFF_XD;    // 1024 floats (overlays bufXd+As)
        const int kq=lane>>3, jg=lane&7;
        const int sg=wid>>2, jh=(wid>>1)&1, kh=wid&1;
        const int sbase=4*sg, jbase=32*jh+jg;
        const int olocal=4*kh+kq;
        u64 acc[4][4];
        #pragma unroll
        for(int m=0;m<4;m++)
            #pragma unroll
            for(int s=0;s<4;s++)acc[m][s]=0ull;

        #pragma unroll 1
        for(int cc=0;cc<4;cc++){
            __syncthreads();
            for(int i4=tid;i4<64*48;i4+=NTHR){
                int j=i4/48,kk=i4-j*48;
                ((float4*)(fcs+j*FCS_S))[kk]=((const float4*)(g_fcw2+(size_t)j*768+cc*192))[kk];
            }
            __syncthreads();
            const int og=8*cc+olocal;
            const float* hbase=sc+og*SC_S+sbase*24;
            const float* wbase=fcs+olocal*24;
            #pragma unroll
            for(int vq=0;vq<6;vq++){
                ulonglong2 w0=*(const ulonglong2*)(wbase+(jbase   )*FCS_S+4*vq);
                ulonglong2 w1=*(const ulonglong2*)(wbase+(jbase+ 8)*FCS_S+4*vq);
                ulonglong2 w2=*(const ulonglong2*)(wbase+(jbase+16)*FCS_S+4*vq);
                ulonglong2 w3=*(const ulonglong2*)(wbase+(jbase+24)*FCS_S+4*vq);
                #pragma unroll
                for(int s=0;s<4;s++){
                    ulonglong2 h=*(const ulonglong2*)(hbase+s*24+4*vq);
                    acc[0][s]=fma2(w0.x,h.x,acc[0][s]); acc[0][s]=fma2(w0.y,h.y,acc[0][s]);
                    acc[1][s]=fma2(w1.x,h.x,acc[1][s]); acc[1][s]=fma2(w1.y,h.y,acc[1][s]);
                    acc[2][s]=fma2(w2.x,h.x,acc[2][s]); acc[2][s]=fma2(w2.y,h.y,acc[2][s]);
                    acc[3][s]=fma2(w3.x,h.x,acc[3][s]); acc[3][s]=fma2(w3.y,h.y,acc[3][s]);
                }
            }
        }
        // reduce over kq (lane bits 3,4)
        float r[4][4];
        #pragma unroll
        for(int m=0;m<4;m++)
            #pragma unroll
            for(int s=0;s<4;s++){
                float2 f=un2(acc[m][s]);
                float v=f.x+f.y;
                v+=__shfl_xor_sync(0xffffffffu,v,8);
                v+=__shfl_xor_sync(0xffffffffu,v,16);
                r[m][s]=v;
            }
        // cross-kh reduction via red
        if(kh==1&&lane<8){
            #pragma unroll
            for(int s=0;s<4;s++)
                #pragma unroll
                for(int m=0;m<4;m++)
                    red[(sbase+s)*64+jbase+8*m]=r[m][s];
        }
        __syncthreads();
        if(kh==0&&lane<8){
            #pragma unroll
            for(int s=0;s<4;s++){
                int t=t0+sbase+s;
                float* op=outp+((size_t)((b*TLEN+t)*2+hand))*64;
                #pragma unroll
                for(int m=0;m<4;m++){
                    int j=jbase+8*m;
                    op[j]=r[m][s]+red[(sbase+s)*64+j]+pp[PP_FCB+j];
                }
            }
        }
    }
}

extern "C" void kernel_launch(void* const* d_in,const int* in_sizes,int n_in,
                              void* d_out,int out_size)
{
    (void)in_sizes;(void)n_in;(void)out_size;
    prep_kernel<<<48,256>>>(
        (const float*)d_in[1],(const float*)d_in[2],(const float*)d_in[3],
        (const float*)d_in[4],(const float*)d_in[5],(const float*)d_in[6],
        (const float*)d_in[7],(const float*)d_in[8],(const float*)d_in[9],
        (const float*)d_in[10],(const float*)d_in[11],(const float*)d_in[12],
        (const float*)d_in[13],(const float*)d_in[14],(const float*)d_in[15],
        (const float*)d_in[16],(const float*)d_in[17],(const float*)d_in[18],
        (const float*)d_in[19],(const float*)d_in[20],(const float*)d_in[21],
        (const float*)d_in[22],(const float*)d_in[23],(const float*)d_in[24]);
    cudaFuncSetAttribute(stgcn_kernel,cudaFuncAttributeMaxDynamicSharedMemorySize,SMEM_BYTES);
    dim3 grid(32,2,64);
    stgcn_kernel<<<grid,NTHR,SMEM_BYTES>>>((const float*)d_in[0],(float*)d_out);
}

// round 11
// speedup vs baseline: 1.1982x; 1.1982x over previous
#include <cuda_runtime.h>
#include <cstddef>

#define TLEN 512
#define NV 21
#define NC 32
#define TC 32
#define NTHR 768

#define HT_S 820      // Ht row stride (205 quads, 5 mod 8)
#define SC_S 772      // sc row stride (193 quads, 1 mod 8)
#define FCS_S 388     // fcs row stride (97 quads, 1 mod 8)

// smem float offsets
#define OFF_R1 0          // Ht[32][820]=26240 ; later fcs[64][388]=24832
#define OFF_R2 26240      // bufAx[36][48]=1728 ; later sc[32][772]=24704
#define OFF_XD 50944      // bufXd[36][48] (1728)
#define OFF_AS 52672      // A (464)
#define OFF_TW 53136      // tw1f (3072)
#define OFF_PP 56208      // pp (640)
#define SMEM_FLOATS 56848
#define SMEM_BYTES (SMEM_FLOATS*4)   // 227392 B

#define PP_TW0 0
#define PP_BK0 192
#define PP_BK1 288
#define PP_TB0 384
#define PP_TB1 416
#define PP_RW 448
#define PP_RB 512
#define PP_FCB 544
#define PP_TOT 608

typedef unsigned long long u64;
__device__ __forceinline__ u64 fma2(u64 a,u64 b,u64 c){u64 d;asm("fma.rn.f32x2 %0,%1,%2,%3;":"=l"(d):"l"(a),"l"(b),"l"(c));return d;}
__device__ __forceinline__ u64 dup2(float v){u64 r;asm("mov.b64 %0,{%1,%1};":"=l"(r):"f"(v));return r;}
__device__ __forceinline__ float2 un2(u64 p){float2 f;asm("mov.b64 {%0,%1},%2;":"=f"(f.x),"=f"(f.y):"l"(p));return f;}

__device__ float g_A[464];
__device__ float g_tw1f[NC*3*NC];
__device__ float g_fcw2[64*768];
__device__ float g_pp[PP_TOT];

__global__ void prep_kernel(
    const float* __restrict__ gcn_w0,const float* __restrict__ gcn_b0,
    const float* __restrict__ tcn_w0,const float* __restrict__ tcn_b0,
    const float* __restrict__ bn_g0,const float* __restrict__ bn_b0,
    const float* __restrict__ bn_m0,const float* __restrict__ bn_v0,
    const float* __restrict__ res_w,const float* __restrict__ res_b,
    const float* __restrict__ res_bn_g,const float* __restrict__ res_bn_b,
    const float* __restrict__ res_bn_m,const float* __restrict__ res_bn_v,
    const float* __restrict__ gcn_w1,const float* __restrict__ gcn_b1,
    const float* __restrict__ tcn_w1,const float* __restrict__ tcn_b1,
    const float* __restrict__ bn_g1,const float* __restrict__ bn_b1,
    const float* __restrict__ bn_m1,const float* __restrict__ bn_v1,
    const float* __restrict__ fc_w,const float* __restrict__ fc_b)
{
    int gtid=blockIdx.x*blockDim.x+threadIdx.x, nthr=gridDim.x*blockDim.x;
    for(int idx=gtid;idx<64*768;idx+=nthr){
        int j=idx/768,kp=idx-j*768,c=kp/24,v=kp-c*24;
        g_fcw2[idx]=(v<NV)?fc_w[j*(NC*NV)+c*NV+v]:0.f;
    }
    for(int idx=gtid;idx<NC*3*NC;idx+=nthr){
        int o=idx&31,ik=idx>>5,i=ik/3,k=ik-i*3;
        float s1=bn_g1[o]*rsqrtf(bn_v1[o]+1e-5f),s=0.f;
        for(int j=0;j<NC;j++) s+=tcn_w1[(o*NC+j)*3+k]*gcn_w1[j*NC+i];
        g_tw1f[(i*3+k)*NC+o]=s*s1;
    }
    if(gtid==0){
        float Ad[NV][NV];
        for(int i=0;i<NV;i++)for(int j=0;j<NV;j++)Ad[i][j]=(i==j)?1.f:0.f;
        const int conn[20][2]={{0,1},{1,2},{2,3},{3,4},{0,5},{5,6},{6,7},{7,8},
            {0,9},{9,10},{10,11},{11,12},{0,13},{13,14},{14,15},{15,16},
            {0,17},{17,18},{18,19},{19,20}};
        for(int e=0;e<20;e++){Ad[conn[e][0]][conn[e][1]]=1.f;Ad[conn[e][1]][conn[e][0]]=1.f;}
        float d[NV];
        for(int i=0;i<NV;i++){float s=0.f;for(int j=0;j<NV;j++)s+=Ad[i][j];d[i]=rsqrtf(s);}
        for(int i=0;i<464;i++)g_A[i]=0.f;
        for(int i=0;i<NV;i++)for(int j=0;j<NV;j++)g_A[i*22+j]=d[i]*Ad[i][j]*d[j];
    }
    if(gtid<NC){
        int o=gtid;
        float s0=bn_g0[o]*rsqrtf(bn_v0[o]+1e-5f);
        float s1=bn_g1[o]*rsqrtf(bn_v1[o]+1e-5f);
        for(int k=0;k<3;k++){
            for(int ci=0;ci<2;ci++){
                float s=0.f;
                for(int i=0;i<NC;i++)s+=tcn_w0[(o*NC+i)*3+k]*gcn_w0[i*2+ci];
                g_pp[PP_TW0+(k*2+ci)*NC+o]=s*s0;
            }
            float sb=0.f;
            for(int i=0;i<NC;i++)sb+=tcn_w0[(o*NC+i)*3+k]*gcn_b0[i];
            g_pp[PP_BK0+k*NC+o]=sb*s0;
            float sb1=0.f;
            for(int j=0;j<NC;j++)sb1+=tcn_w1[(o*NC+j)*3+k]*gcn_b1[j];
            g_pp[PP_BK1+k*NC+o]=sb1*s1;
        }
        g_pp[PP_TB0+o]=(tcn_b0[o]-bn_m0[o])*s0+bn_b0[o];
        g_pp[PP_TB1+o]=(tcn_b1[o]-bn_m1[o])*s1+bn_b1[o];
        float sr=res_bn_g[o]*rsqrtf(res_bn_v[o]+1e-5f);
        g_pp[PP_RW+o]=res_w[o*2+0]*sr;
        g_pp[PP_RW+NC+o]=res_w[o*2+1]*sr;
        g_pp[PP_RB+o]=(res_b[o]-res_bn_m[o])*sr+res_bn_b[o];
    }
    if(gtid>=64&&gtid<128)g_pp[PP_FCB+gtid-64]=fc_b[gtid-64];
}

__global__ __launch_bounds__(NTHR,1)
void stgcn_kernel(const float* __restrict__ x,float* __restrict__ outp)
{
    extern __shared__ float smem[];
    float* R1=smem+OFF_R1;          // Ht / fcs
    float* R2=smem+OFF_R2;          // bufAx / sc
    float* bufXd=smem+OFF_XD;
    float* As=smem+OFF_AS;
    float* tws=smem+OFF_TW;
    float* pp=smem+OFF_PP;

    const int tid=threadIdx.x, lane=tid&31, wid=tid>>5;
    const int t0=blockIdx.x*TC, hand=blockIdx.y, b=blockIdx.z;

    constexpr int DEG[NV]={6,3,3,3,2,3,3,3,2,3,3,3,2,3,3,3,2,3,3,3,2};
    constexpr int NBR[NV][6]={
        {0,1,5,9,13,17},{0,1,2,0,0,0},{1,2,3,0,0,0},{2,3,4,0,0,0},{3,4,0,0,0,0},
        {0,5,6,0,0,0},{5,6,7,0,0,0},{6,7,8,0,0,0},{7,8,0,0,0,0},
        {0,9,10,0,0,0},{9,10,11,0,0,0},{10,11,12,0,0,0},{11,12,0,0,0,0},
        {0,13,14,0,0,0},{13,14,15,0,0,0},{14,15,16,0,0,0},{15,16,0,0,0,0},
        {0,17,18,0,0,0},{17,18,19,0,0,0},{18,19,20,0,0,0},{19,20,0,0,0,0}};

    // prolog
    for(int i=tid;i<464;i+=NTHR)As[i]=g_A[i];
    for(int i=tid;i<NC*3*NC;i+=NTHR)tws[i]=g_tw1f[i];
    for(int i=tid;i<PP_TOT;i+=NTHR)pp[i]=g_pp[i];

    // x fill: bufXd[s][ci*24+v], s=0..35, t=t0+s-2
    for(int idx=tid;idx<36*NV;idx+=NTHR){
        int s=idx/NV,v=idx-s*NV,t=t0+s-2;
        float2 xv=make_float2(0.f,0.f);
        if(t>=0&&t<TLEN)xv=*(const float2*)(x+(((size_t)(b*TLEN+t)*2+hand)*NV+v)*2);
        bufXd[s*48+v]=xv.x; bufXd[s*48+24+v]=xv.y;
    }
    __syncthreads();

    // stage A: A-mix -> bufAx (in R2), 36 tasks over 24 warps
    float* bufAx=R2;
    for(int sA=wid;sA<36;sA+=24){
        if(lane<24){
            float s0=0.f,s1=0.f;
            if(lane<NV){
                const float* Ar=As+lane*22; const float* xr=bufXd+sA*48;
                #pragma unroll
                for(int u=0;u<NV;u++){float a=Ar[u];s0+=a*xr[u];s1+=a*xr[24+u];}
            }
            bufAx[sA*48+lane]=s0; bufAx[sA*48+24+lane]=s1;
        }
    }
    __syncthreads();

    // stage B: folded tcn0+res+relu -> Ht[o][sB*24+..], 34 tasks over 24 warps
    {
        const int o=lane;
        const float bk00=pp[PP_BK0+o],bk02=pp[PP_BK0+64+o];
        const float biasAll=pp[PP_TB0+o]+bk00+pp[PP_BK0+32+o]+bk02+pp[PP_RB+o];
        const u64 rw0d=dup2(pp[PP_RW+o]),rw1d=dup2(pp[PP_RW+32+o]);
        for(int sB=wid;sB<34;sB+=24){
            int t=t0+sB-1;
            float* dst=R1+o*HT_S+sB*24;
            if(t<0||t>=TLEN){
                float4 z=make_float4(0.f,0.f,0.f,0.f);
                #pragma unroll
                for(int m=0;m<6;m++)((float4*)dst)[m]=z;
            }else{
                float bias=biasAll;
                if(t==0)bias-=bk00;
                if(t==TLEN-1)bias-=bk02;
                u64 acc[12],bd=dup2(bias);
                #pragma unroll
                for(int q=0;q<12;q++)acc[q]=bd;
                #pragma unroll
                for(int k=0;k<3;k++)
                    #pragma unroll
                    for(int ci=0;ci<2;ci++){
                        u64 w=dup2(pp[PP_TW0+(k*2+ci)*NC+o]);
                        const ulonglong2* rp=(const ulonglong2*)(bufAx+(sB+k)*48+ci*24);
                        #pragma unroll
                        for(int m=0;m<6;m++){
                            ulonglong2 r2=rp[m];
                            acc[2*m]=fma2(w,r2.x,acc[2*m]);
                            acc[2*m+1]=fma2(w,r2.y,acc[2*m+1]);
                        }
                    }
                const ulonglong2* x0p=(const ulonglong2*)(bufXd+(sB+1)*48);
                const ulonglong2* x1p=(const ulonglong2*)(bufXd+(sB+1)*48+24);
                #pragma unroll
                for(int m=0;m<6;m++){
                    ulonglong2 xa=x0p[m],xb=x1p[m];
                    acc[2*m]=fma2(rw0d,xa.x,acc[2*m]);
                    acc[2*m]=fma2(rw1d,xb.x,acc[2*m]);
                    acc[2*m+1]=fma2(rw0d,xa.y,acc[2*m+1]);
                    acc[2*m+1]=fma2(rw1d,xb.y,acc[2*m+1]);
                }
                float ov[24];
                #pragma unroll
                for(int q=0;q<12;q++){float2 f=un2(acc[q]);ov[2*q]=fmaxf(f.x,0.f);ov[2*q+1]=fmaxf(f.y,0.f);}
                ov[21]=0.f;ov[22]=0.f;ov[23]=0.f;
                #pragma unroll
                for(int m=0;m<6;m++)((float4*)dst)[m]=make_float4(ov[4*m],ov[4*m+1],ov[4*m+2],ov[4*m+3]);
            }
        }
    }
    __syncthreads();   // bufAx dead; sc may be written

    // stage D (GEMM): sc[o][2n]=sum_i,kt W[i,kt,o]*Ht[i][2n+24kt], n=m+96j
    // thread: og=tid/96 (4 o), m=tid%96 (3 warps per og, lane-contiguous m)
    {
        const int og=tid/96, m=tid-og*96;
        u64 acc[4][4];
        #pragma unroll
        for(int oi=0;oi<4;oi++)
            #pragma unroll
            for(int j=0;j<4;j++)acc[oi][j]=0ull;
        #pragma unroll 1
        for(int i=0;i<NC;i++){
            const float* wrow=tws+i*96+4*og;
            const float* hrow=R1+i*HT_S+2*m;
            #pragma unroll
            for(int kt=0;kt<3;kt++){
                float4 wv=*(const float4*)(wrow+kt*32);
                u64 w0=dup2(wv.x),w1=dup2(wv.y),w2=dup2(wv.z),w3=dup2(wv.w);
                #pragma unroll
                for(int j=0;j<4;j++){
                    u64 h=*(const u64*)(hrow+192*j+24*kt);
                    acc[0][j]=fma2(w0,h,acc[0][j]);
                    acc[1][j]=fma2(w1,h,acc[1][j]);
                    acc[2][j]=fma2(w2,h,acc[2][j]);
                    acc[3][j]=fma2(w3,h,acc[3][j]);
                }
            }
        }
        float* sc=R2;
        #pragma unroll
        for(int j=0;j<4;j++){
            int n=m+96*j;
            #pragma unroll
            for(int oi=0;oi<4;oi++)
                *(u64*)(sc+(4*og+oi)*SC_S+2*n)=acc[oi][j];
        }
    }
    __syncthreads();

    // stage D2: A-mix + bias + res + relu, in place on sc rows; 32 tasks/24 warps
    {
        float* sc=R2;
        const int o=lane;
        const float bk10=pp[PP_BK1+o],bk12=pp[PP_BK1+64+o];
        const float biasAll=pp[PP_TB1+o]+bk10+pp[PP_BK1+32+o]+bk12;
        for(int s=wid;s<32;s+=24){
            int t=t0+s;
            float* row=sc+o*SC_S+s*24;
            float qv[24],rres[24];
            #pragma unroll
            for(int m=0;m<6;m++){
                float4 f=((const float4*)row)[m];
                qv[4*m]=f.x;qv[4*m+1]=f.y;qv[4*m+2]=f.z;qv[4*m+3]=f.w;
            }
            const float4* rp=(const float4*)(R1+o*HT_S+(s+1)*24);
            #pragma unroll
            for(int m=0;m<6;m++){
                float4 f=rp[m];
                rres[4*m]=f.x;rres[4*m+1]=f.y;rres[4*m+2]=f.z;rres[4*m+3]=f.w;
            }
            float bias=biasAll;
            if(t==0)bias-=bk10;
            if(t==TLEN-1)bias-=bk12;
            float ov[24];
            #pragma unroll
            for(int v=0;v<NV;v++){
                float p=bias+rres[v];
                #pragma unroll
                for(int j=0;j<6;j++)
                    if(j<DEG[v])p+=As[v*22+NBR[v][j]]*qv[NBR[v][j]];
                ov[v]=fmaxf(p,0.f);
            }
            ov[21]=0.f;ov[22]=0.f;ov[23]=0.f;
            #pragma unroll
            for(int m=0;m<6;m++)((float4*)row)[m]=make_float4(ov[4*m],ov[4*m+1],ov[4*m+2],ov[4*m+3]);
        }
    }
    __syncthreads();   // Ht dead; fcs may overwrite R1

    // stage E: FC 768->64 on warps 0-15 (R7 mapping); staging by all 768 thr.
    // warp = (jh=wid&1, sg=wid>>1): 4 slots, 32 j. lane = (kq=lane>>3, jg=lane&7).
    {
        float* sc=R2;
        float* fcs=R1;
        const int kq=lane>>3, jg=lane&7;
        const int jh=wid&1, sg=wid>>1;
        const int jbase=32*jh+jg;
        const int sbase=4*sg;
        u64 acc[4][4];
        #pragma unroll
        for(int m=0;m<4;m++)
            #pragma unroll
            for(int s=0;s<4;s++)acc[m][s]=0ull;

        #pragma unroll 1
        for(int c=0;c<2;c++){
            __syncthreads();
            for(int i4=tid;i4<64*96;i4+=NTHR){
                int j=i4/96,kk=i4-j*96;
                ((float4*)(fcs+j*FCS_S))[kk]=((const float4*)(g_fcw2+(size_t)j*768+c*384))[kk];
            }
            __syncthreads();
            if(wid<16){
                #pragma unroll
                for(int oi=0;oi<4;oi++){
                    const int oip=(oi+kq)&3;
                    const int olocal=4*kq+oip;
                    const int og=16*c+olocal;
                    const float* hbase=sc+og*SC_S+sbase*24;
                    const float* wbase=fcs+olocal*24;
                    #pragma unroll
                    for(int vq=0;vq<6;vq++){
                        ulonglong2 h0=*(const ulonglong2*)(hbase+0*24+4*vq);
                        ulonglong2 h1=*(const ulonglong2*)(hbase+1*24+4*vq);
                        ulonglong2 h2=*(const ulonglong2*)(hbase+2*24+4*vq);
                        ulonglong2 h3=*(const ulonglong2*)(hbase+3*24+4*vq);
                        ulonglong2 w0=*(const ulonglong2*)(wbase+(jbase   )*FCS_S+4*vq);
                        ulonglong2 w1=*(const ulonglong2*)(wbase+(jbase+ 8)*FCS_S+4*vq);
                        ulonglong2 w2=*(const ulonglong2*)(wbase+(jbase+16)*FCS_S+4*vq);
                        ulonglong2 w3=*(const ulonglong2*)(wbase+(jbase+24)*FCS_S+4*vq);
                        acc[0][0]=fma2(w0.x,h0.x,acc[0][0]); acc[0][0]=fma2(w0.y,h0.y,acc[0][0]);
                        acc[0][1]=fma2(w0.x,h1.x,acc[0][1]); acc[0][1]=fma2(w0.y,h1.y,acc[0][1]);
                        acc[0][2]=fma2(w0.x,h2.x,acc[0][2]); acc[0][2]=fma2(w0.y,h2.y,acc[0][2]);
                        acc[0][3]=fma2(w0.x,h3.x,acc[0][3]); acc[0][3]=fma2(w0.y,h3.y,acc[0][3]);
                        acc[1][0]=fma2(w1.x,h0.x,acc[1][0]); acc[1][0]=fma2(w1.y,h0.y,acc[1][0]);
                        acc[1][1]=fma2(w1.x,h1.x,acc[1][1]); acc[1][1]=fma2(w1.y,h1.y,acc[1][1]);
                        acc[1][2]=fma2(w1.x,h2.x,acc[1][2]); acc[1][2]=fma2(w1.y,h2.y,acc[1][2]);
                        acc[1][3]=fma2(w1.x,h3.x,acc[1][3]); acc[1][3]=fma2(w1.y,h3.y,acc[1][3]);
                        acc[2][0]=fma2(w2.x,h0.x,acc[2][0]); acc[2][0]=fma2(w2.y,h0.y,acc[2][0]);
                        acc[2][1]=fma2(w2.x,h1.x,acc[2][1]); acc[2][1]=fma2(w2.y,h1.y,acc[2][1]);
                        acc[2][2]=fma2(w2.x,h2.x,acc[2][2]); acc[2][2]=fma2(w2.y,h2.y,acc[2][2]);
                        acc[2][3]=fma2(w2.x,h3.x,acc[2][3]); acc[2][3]=fma2(w2.y,h3.y,acc[2][3]);
                        acc[3][0]=fma2(w3.x,h0.x,acc[3][0]); acc[3][0]=fma2(w3.y,h0.y,acc[3][0]);
                        acc[3][1]=fma2(w3.x,h1.x,acc[3][1]); acc[3][1]=fma2(w3.y,h1.y,acc[3][1]);
                        acc[3][2]=fma2(w3.x,h2.x,acc[3][2]); acc[3][2]=fma2(w3.y,h2.y,acc[3][2]);
                        acc[3][3]=fma2(w3.x,h3.x,acc[3][3]); acc[3][3]=fma2(w3.y,h3.y,acc[3][3]);
                    }
                }
            }
        }
        if(wid<16){
            float r[4][4];
            #pragma unroll
            for(int m=0;m<4;m++)
                #pragma unroll
                for(int s=0;s<4;s++){
                    float2 f=un2(acc[m][s]);
                    float v=f.x+f.y;
                    v+=__shfl_xor_sync(0xffffffffu,v,8);
                    v+=__shfl_xor_sync(0xffffffffu,v,16);
                    r[m][s]=v;
                }
            if(lane<8){
                #pragma unroll
                for(int s=0;s<4;s++){
                    int t=t0+sbase+s;
                    float* op=outp+((size_t)((b*TLEN+t)*2+hand))*64;
                    #pragma unroll
                    for(int m=0;m<4;m++){
                        int j=jbase+8*m;
                        op[j]=r[m][s]+pp[PP_FCB+j];
                    }
                }
            }
        }
    }
}

extern "C" void kernel_launch(void* const* d_in,const int* in_sizes,int n_in,
                              void* d_out,int out_size)
{
    (void)in_sizes;(void)n_in;(void)out_size;
    prep_kernel<<<48,256>>>(
        (const float*)d_in[1],(const float*)d_in[2],(const float*)d_in[3],
        (const float*)d_in[4],(const float*)d_in[5],(const float*)d_in[6],
        (const float*)d_in[7],(const float*)d_in[8],(const float*)d_in[9],
        (const float*)d_in[10],(const float*)d_in[11],(const float*)d_in[12],
        (const float*)d_in[13],(const float*)d_in[14],(const float*)d_in[15],
        (const float*)d_in[16],(const float*)d_in[17],(const float*)d_in[18],
        (const float*)d_in[19],(const float*)d_in[20],(const float*)d_in[21],
        (const float*)d_in[22],(const float*)d_in[23],(const float*)d_in[24]);
    cudaFuncSetAttribute(stgcn_kernel,cudaFuncAttributeMaxDynamicSharedMemorySize,SMEM_BYTES);
    dim3 grid(16,2,64);
    stgcn_kernel<<<grid,NTHR,SMEM_BYTES>>>((const float*)d_in[0],(float*)d_out);
}

// round 12
// speedup vs baseline: 1.2238x; 1.0213x over previous
#include <cuda_runtime.h>
#include <cstddef>

#define TLEN 512
#define NV 21
#define NC 32
#define TC 32
#define NTHR 768

#define HT_S 820      // Ht row stride (205 quads, 5 mod 8)
#define SC_S 772      // sc row stride (193 quads, 1 mod 8)
#define FCS_S 388     // fcs row stride (97 quads, 1 mod 8)

// smem float offsets
#define OFF_R1 0          // Ht[32][820]=26240 ; later fcs[64][388]=24832
#define OFF_R2 26240      // bufAx[36][48]=1728 ; later sc[32][772]=24704
#define OFF_XI 50944      // bufXi[36][48] interleaved (1728)
#define OFF_AS 52672      // A [v*22+u] (464)
#define OFF_TW 53136      // tw1f (3072)
#define OFF_PP 56208      // pp (640)
#define OFF_AS2 56848     // A2 [u*24+v] (576)
#define SMEM_FLOATS 57424
#define SMEM_BYTES (SMEM_FLOATS*4)   // 229696 B

#define PP_TW0 0
#define PP_BK0 192
#define PP_BK1 288
#define PP_TB0 384
#define PP_TB1 416
#define PP_RW 448
#define PP_RB 512
#define PP_FCB 544
#define PP_TOT 608

typedef unsigned long long u64;
__device__ __forceinline__ u64 fma2(u64 a,u64 b,u64 c){u64 d;asm("fma.rn.f32x2 %0,%1,%2,%3;":"=l"(d):"l"(a),"l"(b),"l"(c));return d;}
__device__ __forceinline__ u64 dup2(float v){u64 r;asm("mov.b64 %0,{%1,%1};":"=l"(r):"f"(v));return r;}
__device__ __forceinline__ u64 pack2(float lo,float hi){u64 r;asm("mov.b64 %0,{%1,%2};":"=l"(r):"f"(lo),"f"(hi));return r;}
__device__ __forceinline__ float2 un2(u64 p){float2 f;asm("mov.b64 {%0,%1},%2;":"=f"(f.x),"=f"(f.y):"l"(p));return f;}

__device__ float g_A[464];
__device__ float g_A2[576];
__device__ float g_tw1f[NC*3*NC];
__device__ float g_fcw2[64*768];
__device__ float g_pp[PP_TOT];

__global__ void prep_kernel(
    const float* __restrict__ gcn_w0,const float* __restrict__ gcn_b0,
    const float* __restrict__ tcn_w0,const float* __restrict__ tcn_b0,
    const float* __restrict__ bn_g0,const float* __restrict__ bn_b0,
    const float* __restrict__ bn_m0,const float* __restrict__ bn_v0,
    const float* __restrict__ res_w,const float* __restrict__ res_b,
    const float* __restrict__ res_bn_g,const float* __restrict__ res_bn_b,
    const float* __restrict__ res_bn_m,const float* __restrict__ res_bn_v,
    const float* __restrict__ gcn_w1,const float* __restrict__ gcn_b1,
    const float* __restrict__ tcn_w1,const float* __restrict__ tcn_b1,
    const float* __restrict__ bn_g1,const float* __restrict__ bn_b1,
    const float* __restrict__ bn_m1,const float* __restrict__ bn_v1,
    const float* __restrict__ fc_w,const float* __restrict__ fc_b)
{
    int gtid=blockIdx.x*blockDim.x+threadIdx.x, nthr=gridDim.x*blockDim.x;
    for(int idx=gtid;idx<64*768;idx+=nthr){
        int j=idx/768,kp=idx-j*768,c=kp/24,v=kp-c*24;
        g_fcw2[idx]=(v<NV)?fc_w[j*(NC*NV)+c*NV+v]:0.f;
    }
    for(int idx=gtid;idx<NC*3*NC;idx+=nthr){
        int o=idx&31,ik=idx>>5,i=ik/3,k=ik-i*3;
        float s1=bn_g1[o]*rsqrtf(bn_v1[o]+1e-5f),s=0.f;
        for(int j=0;j<NC;j++) s+=tcn_w1[(o*NC+j)*3+k]*gcn_w1[j*NC+i];
        g_tw1f[(i*3+k)*NC+o]=s*s1;
    }
    if(gtid==0){
        float Ad[NV][NV];
        for(int i=0;i<NV;i++)for(int j=0;j<NV;j++)Ad[i][j]=(i==j)?1.f:0.f;
        const int conn[20][2]={{0,1},{1,2},{2,3},{3,4},{0,5},{5,6},{6,7},{7,8},
            {0,9},{9,10},{10,11},{11,12},{0,13},{13,14},{14,15},{15,16},
            {0,17},{17,18},{18,19},{19,20}};
        for(int e=0;e<20;e++){Ad[conn[e][0]][conn[e][1]]=1.f;Ad[conn[e][1]][conn[e][0]]=1.f;}
        float d[NV];
        for(int i=0;i<NV;i++){float s=0.f;for(int j=0;j<NV;j++)s+=Ad[i][j];d[i]=rsqrtf(s);}
        for(int i=0;i<464;i++)g_A[i]=0.f;
        for(int i=0;i<576;i++)g_A2[i]=0.f;
        for(int i=0;i<NV;i++)for(int j=0;j<NV;j++){
            float v=d[i]*Ad[i][j]*d[j];
            g_A[i*22+j]=v;            // [v][u]
            g_A2[j*24+i]=v;           // [u][v] (A symmetric)
        }
    }
    if(gtid<NC){
        int o=gtid;
        float s0=bn_g0[o]*rsqrtf(bn_v0[o]+1e-5f);
        float s1=bn_g1[o]*rsqrtf(bn_v1[o]+1e-5f);
        for(int k=0;k<3;k++){
            for(int ci=0;ci<2;ci++){
                float s=0.f;
                for(int i=0;i<NC;i++)s+=tcn_w0[(o*NC+i)*3+k]*gcn_w0[i*2+ci];
                g_pp[PP_TW0+(k*2+ci)*NC+o]=s*s0;
            }
            float sb=0.f;
            for(int i=0;i<NC;i++)sb+=tcn_w0[(o*NC+i)*3+k]*gcn_b0[i];
            g_pp[PP_BK0+k*NC+o]=sb*s0;
            float sb1=0.f;
            for(int j=0;j<NC;j++)sb1+=tcn_w1[(o*NC+j)*3+k]*gcn_b1[j];
            g_pp[PP_BK1+k*NC+o]=sb1*s1;
        }
        g_pp[PP_TB0+o]=(tcn_b0[o]-bn_m0[o])*s0+bn_b0[o];
        g_pp[PP_TB1+o]=(tcn_b1[o]-bn_m1[o])*s1+bn_b1[o];
        float sr=res_bn_g[o]*rsqrtf(res_bn_v[o]+1e-5f);
        g_pp[PP_RW+o]=res_w[o*2+0]*sr;
        g_pp[PP_RW+NC+o]=res_w[o*2+1]*sr;
        g_pp[PP_RB+o]=(res_b[o]-res_bn_m[o])*sr+res_bn_b[o];
    }
    if(gtid>=64&&gtid<128)g_pp[PP_FCB+gtid-64]=fc_b[gtid-64];
}

__global__ __launch_bounds__(NTHR,1)
void stgcn_kernel(const float* __restrict__ x,float* __restrict__ outp)
{
    extern __shared__ float smem[];
    float* R1=smem+OFF_R1;          // Ht / fcs
    float* R2=smem+OFF_R2;          // bufAx / sc
    float* bufXi=smem+OFF_XI;       // interleaved x [s][v][2]
    float* As=smem+OFF_AS;
    float* tws=smem+OFF_TW;
    float* pp=smem+OFF_PP;
    float* As2=smem+OFF_AS2;

    const int tid=threadIdx.x, lane=tid&31, wid=tid>>5;
    const int t0=blockIdx.x*TC, hand=blockIdx.y, b=blockIdx.z;

    constexpr int DEG[NV]={6,3,3,3,2,3,3,3,2,3,3,3,2,3,3,3,2,3,3,3,2};
    constexpr int NBR[NV][6]={
        {0,1,5,9,13,17},{0,1,2,0,0,0},{1,2,3,0,0,0},{2,3,4,0,0,0},{3,4,0,0,0,0},
        {0,5,6,0,0,0},{5,6,7,0,0,0},{6,7,8,0,0,0},{7,8,0,0,0,0},
        {0,9,10,0,0,0},{9,10,11,0,0,0},{10,11,12,0,0,0},{11,12,0,0,0,0},
        {0,13,14,0,0,0},{13,14,15,0,0,0},{14,15,16,0,0,0},{15,16,0,0,0,0},
        {0,17,18,0,0,0},{17,18,19,0,0,0},{18,19,20,0,0,0},{19,20,0,0,0,0}};

    // prolog
    for(int i=tid;i<464;i+=NTHR)As[i]=g_A[i];
    for(int i=tid;i<576;i+=NTHR)As2[i]=g_A2[i];
    for(int i=tid;i<NC*3*NC;i+=NTHR)tws[i]=g_tw1f[i];
    for(int i=tid;i<PP_TOT;i+=NTHR)pp[i]=g_pp[i];

    // x fill: bufXi[s][v*2+{ci0,ci1}], s=0..35, t=t0+s-2 (interleaved = native)
    for(int idx=tid;idx<36*NV;idx+=NTHR){
        int s=idx/NV,v=idx-s*NV,t=t0+s-2;
        float2 xv=make_float2(0.f,0.f);
        if(t>=0&&t<TLEN)xv=*(const float2*)(x+(((size_t)(b*TLEN+t)*2+hand)*NV+v)*2);
        *(float2*)(bufXi+s*48+v*2)=xv;
    }
    // zero pad v=21..23 (stage B reads full 24-wide rows of bufAx only; bufXi pads unused)
    __syncthreads();

    // stage A: A-mix, lane=v, both ci in one fma2 -> bufAx planar [sA][ci*24+v]
    float* bufAx=R2;
    for(int sA=wid;sA<36;sA+=24){
        u64 acc=0ull;
        if(lane<24){
            if(lane<NV){
                const float* xrow=bufXi+sA*48;
                #pragma unroll
                for(int u=0;u<NV;u++){
                    u64 xu=*(const u64*)(xrow+2*u);          // broadcast
                    acc=fma2(dup2(As2[u*24+lane]),xu,acc);   // lane-distinct A
                }
            }
            float2 f=un2(acc);
            bufAx[sA*48+lane]=f.x;
            bufAx[sA*48+24+lane]=f.y;
        }
    }
    __syncthreads();

    // stage B: folded tcn0 + residual + relu -> Ht[o][sB*24+..]
    {
        const int o=lane;
        const float bk00=pp[PP_BK0+o],bk02=pp[PP_BK0+64+o];
        const float biasAll=pp[PP_TB0+o]+bk00+pp[PP_BK0+32+o]+bk02+pp[PP_RB+o];
        const u64 rwp=pack2(pp[PP_RW+o],pp[PP_RW+32+o]);
        for(int sB=wid;sB<34;sB+=24){
            int t=t0+sB-1;
            float* dst=R1+o*HT_S+sB*24;
            if(t<0||t>=TLEN){
                float4 z=make_float4(0.f,0.f,0.f,0.f);
                #pragma unroll
                for(int m=0;m<6;m++)((float4*)dst)[m]=z;
            }else{
                float bias=biasAll;
                if(t==0)bias-=bk00;
                if(t==TLEN-1)bias-=bk02;
                u64 acc[12],bd=dup2(bias);
                #pragma unroll
                for(int q=0;q<12;q++)acc[q]=bd;
                #pragma unroll
                for(int k=0;k<3;k++)
                    #pragma unroll
                    for(int ci=0;ci<2;ci++){
                        u64 w=dup2(pp[PP_TW0+(k*2+ci)*NC+o]);
                        const ulonglong2* rp=(const ulonglong2*)(bufAx+(sB+k)*48+ci*24);
                        #pragma unroll
                        for(int m=0;m<6;m++){
                            ulonglong2 r2=rp[m];
                            acc[2*m]=fma2(w,r2.x,acc[2*m]);
                            acc[2*m+1]=fma2(w,r2.y,acc[2*m+1]);
                        }
                    }
                float ov[24];
                #pragma unroll
                for(int q=0;q<12;q++){float2 f=un2(acc[q]);ov[2*q]=f.x;ov[2*q+1]=f.y;}
                // residual from interleaved x: r_v = rw0*ci0 + rw1*ci1
                const float* xrow=bufXi+(sB+1)*48;
                #pragma unroll
                for(int v=0;v<NV;v++){
                    u64 xv=*(const u64*)(xrow+2*v);          // broadcast
                    float2 pr=un2(fma2(rwp,xv,0ull));
                    ov[v]=fmaxf(ov[v]+pr.x+pr.y,0.f);
                }
                ov[21]=0.f;ov[22]=0.f;ov[23]=0.f;
                #pragma unroll
                for(int m=0;m<6;m++)((float4*)dst)[m]=make_float4(ov[4*m],ov[4*m+1],ov[4*m+2],ov[4*m+3]);
            }
        }
    }
    __syncthreads();   // bufAx dead; sc may be written

    // stage D (GEMM): sc[o][2n]=sum_i,kt W[i,kt,o]*Ht[i][2n+24kt], n=m+192j
    // thread: og=tid/192 (8 o each, 6 warps/og), m=tid%192, j=0..1
    {
        const int og=tid/192, m=tid-og*192;
        u64 acc[8][2];
        #pragma unroll
        for(int oi=0;oi<8;oi++){acc[oi][0]=0ull;acc[oi][1]=0ull;}
        #pragma unroll 1
        for(int i=0;i<NC;i++){
            const float* wrow=tws+i*96+8*og;
            const float* hrow=R1+i*HT_S+2*m;
            #pragma unroll
            for(int kt=0;kt<3;kt++){
                float4 wa=*(const float4*)(wrow+kt*32);
                float4 wb=*(const float4*)(wrow+kt*32+4);
                u64 h0=*(const u64*)(hrow+24*kt);
                u64 h1=*(const u64*)(hrow+384+24*kt);
                u64 w0=dup2(wa.x),w1=dup2(wa.y),w2=dup2(wa.z),w3=dup2(wa.w);
                u64 w4=dup2(wb.x),w5=dup2(wb.y),w6=dup2(wb.z),w7=dup2(wb.w);
                acc[0][0]=fma2(w0,h0,acc[0][0]); acc[0][1]=fma2(w0,h1,acc[0][1]);
                acc[1][0]=fma2(w1,h0,acc[1][0]); acc[1][1]=fma2(w1,h1,acc[1][1]);
                acc[2][0]=fma2(w2,h0,acc[2][0]); acc[2][1]=fma2(w2,h1,acc[2][1]);
                acc[3][0]=fma2(w3,h0,acc[3][0]); acc[3][1]=fma2(w3,h1,acc[3][1]);
                acc[4][0]=fma2(w4,h0,acc[4][0]); acc[4][1]=fma2(w4,h1,acc[4][1]);
                acc[5][0]=fma2(w5,h0,acc[5][0]); acc[5][1]=fma2(w5,h1,acc[5][1]);
                acc[6][0]=fma2(w6,h0,acc[6][0]); acc[6][1]=fma2(w6,h1,acc[6][1]);
                acc[7][0]=fma2(w7,h0,acc[7][0]); acc[7][1]=fma2(w7,h1,acc[7][1]);
            }
        }
        float* sc=R2;
        #pragma unroll
        for(int j=0;j<2;j++){
            int col=2*(m+192*j);
            #pragma unroll
            for(int oi=0;oi<8;oi++)
                *(u64*)(sc+(8*og+oi)*SC_S+col)=acc[oi][j];
        }
    }
    __syncthreads();

    // stage D2: A-mix + bias + res + relu, in place on sc rows; 32 tasks/24 warps
    {
        float* sc=R2;
        const int o=lane;
        const float bk10=pp[PP_BK1+o],bk12=pp[PP_BK1+64+o];
        const float biasAll=pp[PP_TB1+o]+bk10+pp[PP_BK1+32+o]+bk12;
        for(int s=wid;s<32;s+=24){
            int t=t0+s;
            float* row=sc+o*SC_S+s*24;
            float qv[24],rres[24];
            #pragma unroll
            for(int m=0;m<6;m++){
                float4 f=((const float4*)row)[m];
                qv[4*m]=f.x;qv[4*m+1]=f.y;qv[4*m+2]=f.z;qv[4*m+3]=f.w;
            }
            const float4* rp=(const float4*)(R1+o*HT_S+(s+1)*24);
            #pragma unroll
            for(int m=0;m<6;m++){
                float4 f=rp[m];
                rres[4*m]=f.x;rres[4*m+1]=f.y;rres[4*m+2]=f.z;rres[4*m+3]=f.w;
            }
            float bias=biasAll;
            if(t==0)bias-=bk10;
            if(t==TLEN-1)bias-=bk12;
            float ov[24];
            #pragma unroll
            for(int v=0;v<NV;v++){
                float p=bias+rres[v];
                #pragma unroll
                for(int j=0;j<6;j++)
                    if(j<DEG[v])p+=As[v*22+NBR[v][j]]*qv[NBR[v][j]];
                ov[v]=fmaxf(p,0.f);
            }
            ov[21]=0.f;ov[22]=0.f;ov[23]=0.f;
            #pragma unroll
            for(int m=0;m<6;m++)((float4*)row)[m]=make_float4(ov[4*m],ov[4*m+1],ov[4*m+2],ov[4*m+3]);
        }
    }
    __syncthreads();   // Ht dead; fcs may overwrite R1

    // stage E: FC 768->64 on warps 0-15 (R7 mapping); staging by all 768 thr.
    {
        float* sc=R2;
        float* fcs=R1;
        const int kq=lane>>3, jg=lane&7;
        const int jh=wid&1, sg=wid>>1;
        const int jbase=32*jh+jg;
        const int sbase=4*sg;
        u64 acc[4][4];
        #pragma unroll
        for(int m=0;m<4;m++)
            #pragma unroll
            for(int s=0;s<4;s++)acc[m][s]=0ull;

        #pragma unroll 1
        for(int c=0;c<2;c++){
            __syncthreads();
            for(int i4=tid;i4<64*96;i4+=NTHR){
                int j=i4/96,kk=i4-j*96;
                ((float4*)(fcs+j*FCS_S))[kk]=((const float4*)(g_fcw2+(size_t)j*768+c*384))[kk];
            }
            __syncthreads();
            if(wid<16){
                #pragma unroll
                for(int oi=0;oi<4;oi++){
                    const int oip=(oi+kq)&3;
                    const int olocal=4*kq+oip;
                    const int og=16*c+olocal;
                    const float* hbase=sc+og*SC_S+sbase*24;
                    const float* wbase=fcs+olocal*24;
                    #pragma unroll
                    for(int vq=0;vq<6;vq++){
                        ulonglong2 h0=*(const ulonglong2*)(hbase+0*24+4*vq);
                        ulonglong2 h1=*(const ulonglong2*)(hbase+1*24+4*vq);
                        ulonglong2 h2=*(const ulonglong2*)(hbase+2*24+4*vq);
                        ulonglong2 h3=*(const ulonglong2*)(hbase+3*24+4*vq);
                        ulonglong2 w0=*(const ulonglong2*)(wbase+(jbase   )*FCS_S+4*vq);
                        ulonglong2 w1=*(const ulonglong2*)(wbase+(jbase+ 8)*FCS_S+4*vq);
                        ulonglong2 w2=*(const ulonglong2*)(wbase+(jbase+16)*FCS_S+4*vq);
                        ulonglong2 w3=*(const ulonglong2*)(wbase+(jbase+24)*FCS_S+4*vq);
                        acc[0][0]=fma2(w0.x,h0.x,acc[0][0]); acc[0][0]=fma2(w0.y,h0.y,acc[0][0]);
                        acc[0][1]=fma2(w0.x,h1.x,acc[0][1]); acc[0][1]=fma2(w0.y,h1.y,acc[0][1]);
                        acc[0][2]=fma2(w0.x,h2.x,acc[0][2]); acc[0][2]=fma2(w0.y,h2.y,acc[0][2]);
                        acc[0][3]=fma2(w0.x,h3.x,acc[0][3]); acc[0][3]=fma2(w0.y,h3.y,acc[0][3]);
                        acc[1][0]=fma2(w1.x,h0.x,acc[1][0]); acc[1][0]=fma2(w1.y,h0.y,acc[1][0]);
                        acc[1][1]=fma2(w1.x,h1.x,acc[1][1]); acc[1][1]=fma2(w1.y,h1.y,acc[1][1]);
                        acc[1][2]=fma2(w1.x,h2.x,acc[1][2]); acc[1][2]=fma2(w1.y,h2.y,acc[1][2]);
                        acc[1][3]=fma2(w1.x,h3.x,acc[1][3]); acc[1][3]=fma2(w1.y,h3.y,acc[1][3]);
                        acc[2][0]=fma2(w2.x,h0.x,acc[2][0]); acc[2][0]=fma2(w2.y,h0.y,acc[2][0]);
                        acc[2][1]=fma2(w2.x,h1.x,acc[2][1]); acc[2][1]=fma2(w2.y,h1.y,acc[2][1]);
                        acc[2][2]=fma2(w2.x,h2.x,acc[2][2]); acc[2][2]=fma2(w2.y,h2.y,acc[2][2]);
                        acc[2][3]=fma2(w2.x,h3.x,acc[2][3]); acc[2][3]=fma2(w2.y,h3.y,acc[2][3]);
                        acc[3][0]=fma2(w3.x,h0.x,acc[3][0]); acc[3][0]=fma2(w3.y,h0.y,acc[3][0]);
                        acc[3][1]=fma2(w3.x,h1.x,acc[3][1]); acc[3][1]=fma2(w3.y,h1.y,acc[3][1]);
                        acc[3][2]=fma2(w3.x,h2.x,acc[3][2]); acc[3][2]=fma2(w3.y,h2.y,acc[3][2]);
                        acc[3][3]=fma2(w3.x,h3.x,acc[3][3]); acc[3][3]=fma2(w3.y,h3.y,acc[3][3]);
                    }
                }
            }
        }
        if(wid<16){
            float r[4][4];
            #pragma unroll
            for(int m=0;m<4;m++)
                #pragma unroll
                for(int s=0;s<4;s++){
                    float2 f=un2(acc[m][s]);
                    float v=f.x+f.y;
                    v+=__shfl_xor_sync(0xffffffffu,v,8);
                    v+=__shfl_xor_sync(0xffffffffu,v,16);
                    r[m][s]=v;
                }
            if(lane<8){
                #pragma unroll
                for(int s=0;s<4;s++){
                    int t=t0+sbase+s;
                    float* op=outp+((size_t)((b*TLEN+t)*2+hand))*64;
                    #pragma unroll
                    for(int m=0;m<4;m++){
                        int j=jbase+8*m;
                        op[j]=r[m][s]+pp[PP_FCB+j];
                    }
                }
            }
        }
    }
}

extern "C" void kernel_launch(void* const* d_in,const int* in_sizes,int n_in,
                              void* d_out,int out_size)
{
    (void)in_sizes;(void)n_in;(void)out_size;
    prep_kernel<<<48,256>>>(
        (const float*)d_in[1],(const float*)d_in[2],(const float*)d_in[3],
        (const float*)d_in[4],(const float*)d_in[5],(const float*)d_in[6],
        (const float*)d_in[7],(const float*)d_in[8],(const float*)d_in[9],
        (const float*)d_in[10],(const float*)d_in[11],(const float*)d_in[12],
        (const float*)d_in[13],(const float*)d_in[14],(const float*)d_in[15],
        (const float*)d_in[16],(const float*)d_in[17],(const float*)d_in[18],
        (const float*)d_in[19],(const float*)d_in[20],(const float*)d_in[21],
        (const float*)d_in[22],(const float*)d_in[23],(const float*)d_in[24]);
    cudaFuncSetAttribute(stgcn_kernel,cudaFuncAttributeMaxDynamicSharedMemorySize,SMEM_BYTES);
    dim3 grid(16,2,64);
    stgcn_kernel<<<grid,NTHR,SMEM_BYTES>>>((const float*)d_in[0],(float*)d_out);
}